// round 14
// baseline (speedup 1.0000x reference)
#include <cuda_runtime.h>
#include <cuda_fp16.h>
#include <cstdint>
#include <math.h>

#define BB 2
#define LL 2048
#define DD 1024
#define HH 16
#define DH 64
#define NEGV -10000.0f
#define LOG2E 1.44269504088896f
#define NEGV2 (-14426.9504f)    // NEGV * LOG2E

#define NTOK (BB * LL)          // 4096
#define NELT (BB * LL * DD)     // 4194304
#define WELT (DD * DD)          // 1048576

// ---------------------------------------------------------------------------
// Scratch (__device__ globals per allocation rules)
// ---------------------------------------------------------------------------
__device__ __half g_Xh[NELT];       // x single fp16
__device__ __half g_Wh[4 * WELT];   // Wq,Wk,Wv,Wp single fp16
__device__ __half g_Qh[NELT];       // pre-scaled by 0.125*log2e, hi
__device__ __half g_Ql[NELT];       // pre-scaled, lo residual
__device__ __half g_Kh[NELT];
__device__ __half g_Vh[NELT];
__device__ __half g_Yh[NELT];       // attention out, single fp16

// ---------------------------------------------------------------------------
// PTX helpers (non-'a' features: ldmatrix, mma.sync f16, cp.async)
// ---------------------------------------------------------------------------
__device__ __forceinline__ uint32_t smem_u32(const void* p) {
    uint32_t a;
    asm("{ .reg .u64 t; cvta.to.shared.u64 t, %1; cvt.u32.u64 %0, t; }"
        : "=r"(a) : "l"(p));
    return a;
}

#define LDM4(r0, r1, r2, r3, addr) \
    asm volatile("ldmatrix.sync.aligned.m8n8.x4.shared.b16 {%0,%1,%2,%3}, [%4];" \
                 : "=r"(r0), "=r"(r1), "=r"(r2), "=r"(r3) : "r"(addr))

#define LDMT4(r0, r1, r2, r3, addr) \
    asm volatile("ldmatrix.sync.aligned.m8n8.x4.trans.shared.b16 {%0,%1,%2,%3}, [%4];" \
                 : "=r"(r0), "=r"(r1), "=r"(r2), "=r"(r3) : "r"(addr))

#define MMA16816(acc, a, b0, b1) \
    asm volatile("mma.sync.aligned.m16n8k16.row.col.f32.f16.f16.f32 " \
                 "{%0,%1,%2,%3}, {%4,%5,%6,%7}, {%8,%9}, {%0,%1,%2,%3};" \
                 : "+f"((acc)[0]), "+f"((acc)[1]), "+f"((acc)[2]), "+f"((acc)[3]) \
                 : "r"((a)[0]), "r"((a)[1]), "r"((a)[2]), "r"((a)[3]), \
                   "r"(b0), "r"(b1))

#define CP16(dst, src) \
    asm volatile("cp.async.cg.shared.global [%0], [%1], 16;" \
                 :: "r"(dst), "l"(src) : "memory")
#define CP_COMMIT() asm volatile("cp.async.commit_group;" ::: "memory")
#define CP_WAIT0()  asm volatile("cp.async.wait_group 0;" ::: "memory")
#define CP_WAIT1()  asm volatile("cp.async.wait_group 1;" ::: "memory")

// split a,b into packed fp16 hi pair + residual lo pair
__device__ __forceinline__ void split2h(float a, float b, uint32_t& hi, uint32_t& lo) {
    __half2 h = __floats2half2_rn(a, b);
    __half2 l = __floats2half2_rn(a - __half2float(h.x), b - __half2float(h.y));
    hi = *(uint32_t*)&h;
    lo = *(uint32_t*)&l;
}

// ---------------------------------------------------------------------------
// fused conversion: 8 WELT-sized slots (4 weights + 4 quarters of x)
// ---------------------------------------------------------------------------
struct CPtrs8 { const float* src[8]; __half* dst[8]; };

__global__ __launch_bounds__(256) void conv8(CPtrs8 c)
{
    const float* src = c.src[blockIdx.y];
    __half* d = c.dst[blockIdx.y];
    int idx = (blockIdx.x * 256 + threadIdx.x) * 4;
    float4 v = *(const float4*)&src[idx];
    __half h[4] = {__float2half_rn(v.x), __float2half_rn(v.y),
                   __float2half_rn(v.z), __float2half_rn(v.w)};
    *(uint2*)&d[idx] = *(uint2*)h;
}

// ---------------------------------------------------------------------------
// fp16 1-term GEMM: C = A @ W^T + bias (A, W single fp16).
// Tile 128x128, BK=64, 8 warps (4Mx2N), warp tile 32x64. Pitch 72.
// 2-stage cp.async, one barrier per chunk. Fused QKV via blockIdx.z.
// ---------------------------------------------------------------------------
#define GPITCH 72
#define GT_B   (128 * GPITCH * 2)        // 18432
#define GSTAGE (2 * GT_B)                // 36864 (A, W)
#define GEMM_SMEM (2 * GSTAGE)           // 73728

struct GArgs {
    const __half* W[3];
    const float*  bias[3];
    __half* oh[3];
    __half* ol[3];
    float oscale[3];
};

__global__ __launch_bounds__(256) void gemm_mma(
    const __half* __restrict__ A,
    GArgs args, float* __restrict__ Cf, int M, int N, int K)
{
    extern __shared__ char sraw[];

    const int z = blockIdx.z;
    const __half* W   = args.W[z];
    const float* bias = args.bias[z];
    __half* Chi = args.oh[z];
    __half* Clo = args.ol[z];
    const float osc = args.oscale[z];

    const int tid  = threadIdx.x;
    const int lane = tid & 31;
    const int wid  = tid >> 5;
    const int wm   = (wid >> 1) * 32;
    const int wn   = (wid & 1) * 64;
    const int rowBase = blockIdx.y * 128;
    const int colBase = blockIdx.x * 128;

    const uint32_t sbase = smem_u32(sraw);

    const uint32_t aOff = ((uint32_t)(wm + (lane & 15)) * GPITCH + ((lane >> 4) << 3)) * 2;
    const uint32_t bOff = ((uint32_t)(wn + (lane & 7) + ((lane >> 4) << 3)) * GPITCH
                          + (((lane >> 3) & 1) << 3)) * 2;

    float acc[2][8][4];
#pragma unroll
    for (int i = 0; i < 2; i++)
#pragma unroll
        for (int j = 0; j < 8; j++)
#pragma unroll
            for (int v = 0; v < 4; v++) acc[i][j][v] = 0.0f;

    const int nc = K >> 6;

    auto load_chunk = [&](int kc, int stage) {
        const uint32_t sb = sbase + stage * GSTAGE;
        const __half* srcs[2] = {A, W};
        const int rbs[2] = {rowBase, colBase};
#pragma unroll
        for (int t = 0; t < 2; t++) {
            const __half* s = srcs[t];
            const int rb = rbs[t];
            const uint32_t tb = sb + t * GT_B;
#pragma unroll
            for (int i = 0; i < 4; i++) {
                int idx = tid + i * 256;
                int r = idx >> 3;
                int c = idx & 7;
                CP16(tb + (r * GPITCH + c * 8) * 2,
                     s + (size_t)(rb + r) * K + kc * 64 + c * 8);
            }
        }
        CP_COMMIT();
    };

    load_chunk(0, 0);

    for (int kc = 0; kc < nc; kc++) {
        CP_WAIT0();
        __syncthreads();
        if (kc + 1 < nc) load_chunk(kc + 1, (kc + 1) & 1);

        const uint32_t sb = sbase + (kc & 1) * GSTAGE;
        const uint32_t sA = sb;
        const uint32_t sW = sb + GT_B;

#pragma unroll
        for (int kk = 0; kk < 4; kk++) {
            const uint32_t kByte = kk * 32;
            uint32_t ah[2][4];
#pragma unroll
            for (int mi = 0; mi < 2; mi++) {
                uint32_t ao = aOff + mi * 16 * GPITCH * 2 + kByte;
                LDM4(ah[mi][0], ah[mi][1], ah[mi][2], ah[mi][3], sA + ao);
            }
#pragma unroll
            for (int nb2 = 0; nb2 < 4; nb2++) {
                uint32_t bo = bOff + nb2 * 16 * GPITCH * 2 + kByte;
                uint32_t bh[4];
                LDM4(bh[0], bh[1], bh[2], bh[3], sW + bo);
#pragma unroll
                for (int mi = 0; mi < 2; mi++) {
                    MMA16816(acc[mi][nb2 * 2 + 0], ah[mi], bh[0], bh[1]);
                    MMA16816(acc[mi][nb2 * 2 + 1], ah[mi], bh[2], bh[3]);
                }
            }
        }
    }

    const int g  = lane >> 2;
    const int tc = (lane & 3) * 2;
#pragma unroll
    for (int mi = 0; mi < 2; mi++) {
#pragma unroll
        for (int nb = 0; nb < 8; nb++) {
            int col = colBase + wn + nb * 8 + tc;
            float b0 = bias[col], b1 = bias[col + 1];
            int row0 = rowBase + wm + mi * 16 + g;
            float y0 = (acc[mi][nb][0] + b0) * osc, y1 = (acc[mi][nb][1] + b1) * osc;
            float y2 = (acc[mi][nb][2] + b0) * osc, y3 = (acc[mi][nb][3] + b1) * osc;
            if (Cf) {
                float2 o0 = {y0, y1};
                *(float2*)&Cf[(size_t)row0 * N + col] = o0;
                float2 o1 = {y2, y3};
                *(float2*)&Cf[(size_t)(row0 + 8) * N + col] = o1;
            } else if (Clo) {
                uint32_t h, l;
                split2h(y0, y1, h, l);
                *(uint32_t*)&Chi[(size_t)row0 * N + col] = h;
                *(uint32_t*)&Clo[(size_t)row0 * N + col] = l;
                split2h(y2, y3, h, l);
                *(uint32_t*)&Chi[(size_t)(row0 + 8) * N + col] = h;
                *(uint32_t*)&Clo[(size_t)(row0 + 8) * N + col] = l;
            } else {
                __half2 h0 = __floats2half2_rn(y0, y1);
                *(uint32_t*)&Chi[(size_t)row0 * N + col] = *(uint32_t*)&h0;
                __half2 h1 = __floats2half2_rn(y2, y3);
                *(uint32_t*)&Chi[(size_t)(row0 + 8) * N + col] = *(uint32_t*)&h1;
            }
        }
    }
}

// ---------------------------------------------------------------------------
// fp16 flash attention, log2-domain softmax. Q dual (pre-scaled by
// 0.125*log2e), K/V single, P single, Y single. BQ=128, BK=64, 8 warps.
// 3-stage cp.async KV pipeline (R11 config), no occupancy cap.
// ---------------------------------------------------------------------------
#define AP 72
#define AKV_T (64 * AP * 2)              // 9216
#define ASTG  (2 * AKV_T)                // 18432 (Kh + Vh)
#define AQ_B  (128 * AP * 2)             // 18432
#define AKV_B (2 * AQ_B)                 // 36864
#define APAD_B (AKV_B + 3 * ASTG)        // 92160
#define ATTN_SMEM (APAD_B + 3 * 64 * 4)  // 92928

__global__ __launch_bounds__(256) void attn_mma(
    const __half* __restrict__ Qh, const __half* __restrict__ Ql,
    const __half* __restrict__ Kh, const __half* __restrict__ Vh,
    const int* __restrict__ msk,
    __half* __restrict__ Yh)
{
    extern __shared__ char sraw[];
    float* pads = (float*)(sraw + APAD_B);

    const int tid  = threadIdx.x;
    const int lane = tid & 31;
    const int wid  = tid >> 5;
    const int wm   = wid * 16;
    const int qt   = gridDim.x - 1 - blockIdx.x;   // heavy tiles first
    const int bh   = blockIdx.y;
    const int b    = bh / HH;
    const int h    = bh % HH;

    const uint32_t sbase = smem_u32(sraw);
    const uint32_t sQH = sbase, sQL = sbase + AQ_B;

    auto load_kv = [&](int jt, int stage) {
        const size_t krow0 = (size_t)b * LL + (size_t)jt * 64;
        const uint32_t sb = sbase + AKV_B + stage * ASTG;
#pragma unroll
        for (int i = 0; i < 2; i++) {
            int idx = tid + i * 256;      // 0..511
            int r = idx >> 3;
            int c = idx & 7;
            const size_t gsrc = (krow0 + r) * DD + h * DH + c * 8;
            uint32_t so = (r * AP + c * 8) * 2;
            CP16(sb + so,          Kh + gsrc);
            CP16(sb + AKV_T + so,  Vh + gsrc);
        }
        CP_COMMIT();
    };

    // Q tile (128 x 64) hi/lo
    const size_t qrow0 = (size_t)b * LL + (size_t)qt * 128;
#pragma unroll
    for (int i = 0; i < 4; i++) {
        int idx = tid + i * 256;
        int r = idx >> 3;
        int c = idx & 7;
        size_t gsrc = (qrow0 + r) * DD + h * DH + c * 8;
        CP16(sQH + (r * AP + c * 8) * 2, Qh + gsrc);
        CP16(sQL + (r * AP + c * 8) * 2, Ql + gsrc);
    }
    CP_COMMIT();
    const int jtMax = 2 * qt + 1;
    load_kv(0, 0);
    if (1 <= jtMax) load_kv(1, 1); else CP_COMMIT();

    const uint32_t aOff = ((uint32_t)(wm + (lane & 15)) * AP + ((lane >> 4) << 3)) * 2;
    const uint32_t bOff = ((uint32_t)((lane & 7) + ((lane >> 4) << 3)) * AP
                          + (((lane >> 3) & 1) << 3)) * 2;
    const uint32_t vOff = ((uint32_t)(((lane >> 3) & 1) * 8 + (lane & 7)) * AP
                          + ((lane >> 4) << 3)) * 2;

    const int g   = lane >> 2;
    const int tc2 = (lane & 3) * 2;
    const int qg0 = qt * 128 + wm + g;
    const int qg1 = qg0 + 8;

    float m0 = -1e30f, m1 = -1e30f, l0 = 0.0f, l1 = 0.0f;
    float oacc[8][4];
#pragma unroll
    for (int i = 0; i < 8; i++)
#pragma unroll
        for (int v = 0; v < 4; v++) oacc[i][v] = 0.0f;

    for (int jt = 0; jt <= jtMax; jt++) {
        const int cur = jt % 3;
        if (tid < 64)
            pads[cur * 64 + tid] =
                (1.0f - (float)msk[b * LL + jt * 64 + tid]) * NEGV2;

        CP_WAIT1();
        __syncthreads();
        if (jt + 2 <= jtMax) load_kv(jt + 2, (jt + 2) % 3);

        const uint32_t sb  = sbase + AKV_B + cur * ASTG;
        const uint32_t sKH = sb;
        const uint32_t sVH = sb + AKV_T;
        const float* padc = pads + cur * 64;

        // ---- S = (Qh+Ql) @ Kh^T  (log2-domain: Q pre-scaled by s*log2e) ----
        float sacc[8][4];
#pragma unroll
        for (int i = 0; i < 8; i++)
#pragma unroll
            for (int v = 0; v < 4; v++) sacc[i][v] = 0.0f;

#pragma unroll
        for (int kk = 0; kk < 4; kk++) {
            const uint32_t kByte = kk * 32;
            uint32_t ah[4], al[4];
            LDM4(ah[0], ah[1], ah[2], ah[3], sQH + aOff + kByte);
            LDM4(al[0], al[1], al[2], al[3], sQL + aOff + kByte);
#pragma unroll
            for (int nb2 = 0; nb2 < 4; nb2++) {
                uint32_t bo = bOff + nb2 * 16 * AP * 2 + kByte;
                uint32_t kh[4];
                LDM4(kh[0], kh[1], kh[2], kh[3], sKH + bo);
                MMA16816(sacc[nb2 * 2 + 0], ah, kh[0], kh[1]);
                MMA16816(sacc[nb2 * 2 + 1], ah, kh[2], kh[3]);
                MMA16816(sacc[nb2 * 2 + 0], al, kh[0], kh[1]);
                MMA16816(sacc[nb2 * 2 + 1], al, kh[2], kh[3]);
            }
        }

        // ---- causal (warp-uniform skip for interior tiles) + pad mask ----
        if (jt * 64 + 63 > qt * 128 + wm) {
#pragma unroll
            for (int nb = 0; nb < 8; nb++) {
                int kgA = jt * 64 + nb * 8 + tc2;
                float p0 = padc[nb * 8 + tc2];
                float p1 = padc[nb * 8 + tc2 + 1];
                float v0 = sacc[nb][0]; if (kgA     > qg0) v0 = NEGV2; v0 += p0;
                float v1 = sacc[nb][1]; if (kgA + 1 > qg0) v1 = NEGV2; v1 += p1;
                float v2 = sacc[nb][2]; if (kgA     > qg1) v2 = NEGV2; v2 += p0;
                float v3 = sacc[nb][3]; if (kgA + 1 > qg1) v3 = NEGV2; v3 += p1;
                sacc[nb][0] = v0; sacc[nb][1] = v1; sacc[nb][2] = v2; sacc[nb][3] = v3;
            }
        } else {
#pragma unroll
            for (int nb = 0; nb < 8; nb++) {
                float p0 = padc[nb * 8 + tc2];
                float p1 = padc[nb * 8 + tc2 + 1];
                sacc[nb][0] += p0; sacc[nb][1] += p1;
                sacc[nb][2] += p0; sacc[nb][3] += p1;
            }
        }

        // ---- online softmax (base-2) ----
        float rmax0 = -1e30f, rmax1 = -1e30f;
#pragma unroll
        for (int nb = 0; nb < 8; nb++) {
            rmax0 = fmaxf(rmax0, fmaxf(sacc[nb][0], sacc[nb][1]));
            rmax1 = fmaxf(rmax1, fmaxf(sacc[nb][2], sacc[nb][3]));
        }
#pragma unroll
        for (int o = 1; o <= 2; o <<= 1) {
            rmax0 = fmaxf(rmax0, __shfl_xor_sync(0xffffffffu, rmax0, o));
            rmax1 = fmaxf(rmax1, __shfl_xor_sync(0xffffffffu, rmax1, o));
        }
        float m0n = fmaxf(m0, rmax0), m1n = fmaxf(m1, rmax1);
        float a0 = exp2f(m0 - m0n), a1 = exp2f(m1 - m1n);
        float sum0 = 0.0f, sum1 = 0.0f;
#pragma unroll
        for (int nb = 0; nb < 8; nb++) {
            sacc[nb][0] = exp2f(sacc[nb][0] - m0n);
            sacc[nb][1] = exp2f(sacc[nb][1] - m0n);
            sacc[nb][2] = exp2f(sacc[nb][2] - m1n);
            sacc[nb][3] = exp2f(sacc[nb][3] - m1n);
            sum0 += sacc[nb][0] + sacc[nb][1];
            sum1 += sacc[nb][2] + sacc[nb][3];
        }
#pragma unroll
        for (int o = 1; o <= 2; o <<= 1) {
            sum0 += __shfl_xor_sync(0xffffffffu, sum0, o);
            sum1 += __shfl_xor_sync(0xffffffffu, sum1, o);
        }
        l0 = l0 * a0 + sum0; m0 = m0n;
        l1 = l1 * a1 + sum1; m1 = m1n;
#pragma unroll
        for (int nb = 0; nb < 8; nb++) {
            oacc[nb][0] *= a0; oacc[nb][1] *= a0;
            oacc[nb][2] *= a1; oacc[nb][3] *= a1;
        }

        // ---- O += P @ Vh (P single fp16) ----
#pragma unroll
        for (int kb = 0; kb < 4; kb++) {
            uint32_t ph[4];
            {
                __half2 t0 = __floats2half2_rn(sacc[2 * kb][0],     sacc[2 * kb][1]);
                __half2 t1 = __floats2half2_rn(sacc[2 * kb][2],     sacc[2 * kb][3]);
                __half2 t2 = __floats2half2_rn(sacc[2 * kb + 1][0], sacc[2 * kb + 1][1]);
                __half2 t3 = __floats2half2_rn(sacc[2 * kb + 1][2], sacc[2 * kb + 1][3]);
                ph[0] = *(uint32_t*)&t0; ph[1] = *(uint32_t*)&t1;
                ph[2] = *(uint32_t*)&t2; ph[3] = *(uint32_t*)&t3;
            }
#pragma unroll
            for (int nb2 = 0; nb2 < 4; nb2++) {
                uint32_t vo = vOff + (kb * 16 * AP + nb2 * 16) * 2;
                uint32_t vh[4];
                LDMT4(vh[0], vh[1], vh[2], vh[3], sVH + vo);
                MMA16816(oacc[nb2 * 2 + 0], ph, vh[0], vh[1]);
                MMA16816(oacc[nb2 * 2 + 1], ph, vh[2], vh[3]);
            }
        }
    }

    // ---- finalize + write Y (single fp16) ----
    float inv0 = 1.0f / l0, inv1 = 1.0f / l1;
    const size_t row0 = qrow0 + wm + g;
#pragma unroll
    for (int nb = 0; nb < 8; nb++) {
        int col = h * DH + nb * 8 + tc2;
        __half2 h0 = __floats2half2_rn(oacc[nb][0] * inv0, oacc[nb][1] * inv0);
        *(uint32_t*)&Yh[row0 * DD + col] = *(uint32_t*)&h0;
        __half2 h1 = __floats2half2_rn(oacc[nb][2] * inv1, oacc[nb][3] * inv1);
        *(uint32_t*)&Yh[(row0 + 8) * DD + col] = *(uint32_t*)&h1;
    }
}

// ---------------------------------------------------------------------------
extern "C" void kernel_launch(void* const* d_in, const int* in_sizes, int n_in,
                              void* d_out, int out_size)
{
    const float* x  = (const float*)d_in[0];
    const int*   m  = (const int*)d_in[1];
    const float* Wq = (const float*)d_in[2];
    const float* bq = (const float*)d_in[3];
    const float* Wk = (const float*)d_in[4];
    const float* bk = (const float*)d_in[5];
    const float* Wv = (const float*)d_in[6];
    const float* bv = (const float*)d_in[7];
    const float* Wp = (const float*)d_in[8];
    const float* bp = (const float*)d_in[9];
    float* out = (float*)d_out;

    __half *xh, *wh, *qh, *ql, *kh, *vh, *yh;
    cudaGetSymbolAddress((void**)&xh, g_Xh);
    cudaGetSymbolAddress((void**)&wh, g_Wh);
    cudaGetSymbolAddress((void**)&qh, g_Qh);
    cudaGetSymbolAddress((void**)&ql, g_Ql);
    cudaGetSymbolAddress((void**)&kh, g_Kh);
    cudaGetSymbolAddress((void**)&vh, g_Vh);
    cudaGetSymbolAddress((void**)&yh, g_Yh);

    static bool attr_set = false;
    if (!attr_set) {
        cudaFuncSetAttribute(gemm_mma,
                             cudaFuncAttributeMaxDynamicSharedMemorySize, GEMM_SMEM);
        cudaFuncSetAttribute(attn_mma,
                             cudaFuncAttributeMaxDynamicSharedMemorySize, ATTN_SMEM);
        attr_set = true;
    }

    // One fused conversion launch: 4 weights + 4 quarters of x (NELT==4*WELT)
    CPtrs8 c8;
    c8.src[0] = Wq; c8.dst[0] = wh + 0 * WELT;
    c8.src[1] = Wk; c8.dst[1] = wh + 1 * WELT;
    c8.src[2] = Wv; c8.dst[2] = wh + 2 * WELT;
    c8.src[3] = Wp; c8.dst[3] = wh + 3 * WELT;
    for (int i = 0; i < 4; i++) {
        c8.src[4 + i] = x + (size_t)i * WELT;
        c8.dst[4 + i] = xh + (size_t)i * WELT;
    }
    dim3 cgrid(WELT / 4 / 256, 8);
    conv8<<<cgrid, 256>>>(c8);

    // Fused QKV (z = 0:Q dual out, pre-scaled by 0.125*log2e; 1:K; 2:V)
    GArgs qkv;
    qkv.W[0] = wh + 0 * WELT; qkv.W[1] = wh + 1 * WELT; qkv.W[2] = wh + 2 * WELT;
    qkv.bias[0] = bq; qkv.bias[1] = bk; qkv.bias[2] = bv;
    qkv.oh[0] = qh;  qkv.oh[1] = kh;  qkv.oh[2] = vh;
    qkv.ol[0] = ql;  qkv.ol[1] = nullptr; qkv.ol[2] = nullptr;
    qkv.oscale[0] = 0.125f * LOG2E; qkv.oscale[1] = 1.0f; qkv.oscale[2] = 1.0f;
    dim3 qgrid(DD / 128, NTOK / 128, 3);   // (8, 32, 3)
    gemm_mma<<<qgrid, 256, GEMM_SMEM>>>(xh, qkv, nullptr, NTOK, DD, DD);

    dim3 agrid(LL / 128, BB * HH);         // (16, 32)
    attn_mma<<<agrid, 256, ATTN_SMEM>>>(qh, ql, kh, vh, m, yh);

    GArgs proj;
    proj.W[0] = wh + 3 * WELT; proj.W[1] = nullptr; proj.W[2] = nullptr;
    proj.bias[0] = bp; proj.bias[1] = nullptr; proj.bias[2] = nullptr;
    proj.oh[0] = nullptr; proj.oh[1] = nullptr; proj.oh[2] = nullptr;
    proj.ol[0] = nullptr; proj.ol[1] = nullptr; proj.ol[2] = nullptr;
    proj.oscale[0] = 1.0f; proj.oscale[1] = 1.0f; proj.oscale[2] = 1.0f;
    dim3 pgrid(DD / 128, NTOK / 128, 1);   // (8, 32, 1)
    gemm_mma<<<pgrid, 256, GEMM_SMEM>>>(yh, proj, out, NTOK, DD, DD);
}

// round 15
// speedup vs baseline: 1.0165x; 1.0165x over previous
#include <cuda_runtime.h>
#include <cuda_fp16.h>
#include <cstdint>
#include <math.h>

#define BB 2
#define LL 2048
#define DD 1024
#define HH 16
#define DH 64
#define NEGV -10000.0f
#define LOG2E 1.44269504088896f
#define NEGV2 (-14426.9504f)    // NEGV * LOG2E

#define NTOK (BB * LL)          // 4096
#define NELT (BB * LL * DD)     // 4194304
#define WELT (DD * DD)          // 1048576

// ---------------------------------------------------------------------------
// Scratch (__device__ globals per allocation rules)
// ---------------------------------------------------------------------------
__device__ __half g_Xh[NELT];       // x single fp16
__device__ __half g_Wh[4 * WELT];   // Wq,Wk,Wv,Wp single fp16
__device__ __half g_Qh[NELT];       // pre-scaled by 0.125*log2e, hi
__device__ __half g_Ql[NELT];       // pre-scaled, lo residual
__device__ __half g_Kh[NELT];
__device__ __half g_Vh[NELT];
__device__ __half g_Yh[NELT];       // attention out, single fp16

// ---------------------------------------------------------------------------
// PTX helpers (non-'a' features: ldmatrix, mma.sync f16, cp.async)
// ---------------------------------------------------------------------------
__device__ __forceinline__ uint32_t smem_u32(const void* p) {
    uint32_t a;
    asm("{ .reg .u64 t; cvta.to.shared.u64 t, %1; cvt.u32.u64 %0, t; }"
        : "=r"(a) : "l"(p));
    return a;
}

// single-MUFU base-2 exponential (EX2), the instruction the log2-domain
// softmax is designed around. exp2f() w/o fast-math is a slow accurate seq.
__device__ __forceinline__ float ex2(float x) {
    float r;
    asm("ex2.approx.ftz.f32 %0, %1;" : "=f"(r) : "f"(x));
    return r;
}

#define LDM4(r0, r1, r2, r3, addr) \
    asm volatile("ldmatrix.sync.aligned.m8n8.x4.shared.b16 {%0,%1,%2,%3}, [%4];" \
                 : "=r"(r0), "=r"(r1), "=r"(r2), "=r"(r3) : "r"(addr))

#define LDMT4(r0, r1, r2, r3, addr) \
    asm volatile("ldmatrix.sync.aligned.m8n8.x4.trans.shared.b16 {%0,%1,%2,%3}, [%4];" \
                 : "=r"(r0), "=r"(r1), "=r"(r2), "=r"(r3) : "r"(addr))

#define MMA16816(acc, a, b0, b1) \
    asm volatile("mma.sync.aligned.m16n8k16.row.col.f32.f16.f16.f32 " \
                 "{%0,%1,%2,%3}, {%4,%5,%6,%7}, {%8,%9}, {%0,%1,%2,%3};" \
                 : "+f"((acc)[0]), "+f"((acc)[1]), "+f"((acc)[2]), "+f"((acc)[3]) \
                 : "r"((a)[0]), "r"((a)[1]), "r"((a)[2]), "r"((a)[3]), \
                   "r"(b0), "r"(b1))

#define CP16(dst, src) \
    asm volatile("cp.async.cg.shared.global [%0], [%1], 16;" \
                 :: "r"(dst), "l"(src) : "memory")
#define CP_COMMIT() asm volatile("cp.async.commit_group;" ::: "memory")
#define CP_WAIT0()  asm volatile("cp.async.wait_group 0;" ::: "memory")
#define CP_WAIT1()  asm volatile("cp.async.wait_group 1;" ::: "memory")

// split a,b into packed fp16 hi pair + residual lo pair
__device__ __forceinline__ void split2h(float a, float b, uint32_t& hi, uint32_t& lo) {
    __half2 h = __floats2half2_rn(a, b);
    __half2 l = __floats2half2_rn(a - __half2float(h.x), b - __half2float(h.y));
    hi = *(uint32_t*)&h;
    lo = *(uint32_t*)&l;
}

// ---------------------------------------------------------------------------
// fused conversion: 8 WELT-sized slots (4 weights + 4 quarters of x)
// ---------------------------------------------------------------------------
struct CPtrs8 { const float* src[8]; __half* dst[8]; };

__global__ __launch_bounds__(256) void conv8(CPtrs8 c)
{
    const float* src = c.src[blockIdx.y];
    __half* d = c.dst[blockIdx.y];
    int idx = (blockIdx.x * 256 + threadIdx.x) * 4;
    float4 v = *(const float4*)&src[idx];
    __half h[4] = {__float2half_rn(v.x), __float2half_rn(v.y),
                   __float2half_rn(v.z), __float2half_rn(v.w)};
    *(uint2*)&d[idx] = *(uint2*)h;
}

// ---------------------------------------------------------------------------
// fp16 1-term GEMM: C = A @ W^T + bias (A, W single fp16).
// Tile 128x128, BK=64, 8 warps (4Mx2N), warp tile 32x64. Pitch 72.
// 2-stage cp.async, one barrier per chunk. Fused QKV via blockIdx.z.
// ---------------------------------------------------------------------------
#define GPITCH 72
#define GT_B   (128 * GPITCH * 2)        // 18432
#define GSTAGE (2 * GT_B)                // 36864 (A, W)
#define GEMM_SMEM (2 * GSTAGE)           // 73728

struct GArgs {
    const __half* W[3];
    const float*  bias[3];
    __half* oh[3];
    __half* ol[3];
    float oscale[3];
};

__global__ __launch_bounds__(256) void gemm_mma(
    const __half* __restrict__ A,
    GArgs args, float* __restrict__ Cf, int M, int N, int K)
{
    extern __shared__ char sraw[];

    const int z = blockIdx.z;
    const __half* W   = args.W[z];
    const float* bias = args.bias[z];
    __half* Chi = args.oh[z];
    __half* Clo = args.ol[z];
    const float osc = args.oscale[z];

    const int tid  = threadIdx.x;
    const int lane = tid & 31;
    const int wid  = tid >> 5;
    const int wm   = (wid >> 1) * 32;
    const int wn   = (wid & 1) * 64;
    const int rowBase = blockIdx.y * 128;
    const int colBase = blockIdx.x * 128;

    const uint32_t sbase = smem_u32(sraw);

    const uint32_t aOff = ((uint32_t)(wm + (lane & 15)) * GPITCH + ((lane >> 4) << 3)) * 2;
    const uint32_t bOff = ((uint32_t)(wn + (lane & 7) + ((lane >> 4) << 3)) * GPITCH
                          + (((lane >> 3) & 1) << 3)) * 2;

    float acc[2][8][4];
#pragma unroll
    for (int i = 0; i < 2; i++)
#pragma unroll
        for (int j = 0; j < 8; j++)
#pragma unroll
            for (int v = 0; v < 4; v++) acc[i][j][v] = 0.0f;

    const int nc = K >> 6;

    auto load_chunk = [&](int kc, int stage) {
        const uint32_t sb = sbase + stage * GSTAGE;
        const __half* srcs[2] = {A, W};
        const int rbs[2] = {rowBase, colBase};
#pragma unroll
        for (int t = 0; t < 2; t++) {
            const __half* s = srcs[t];
            const int rb = rbs[t];
            const uint32_t tb = sb + t * GT_B;
#pragma unroll
            for (int i = 0; i < 4; i++) {
                int idx = tid + i * 256;
                int r = idx >> 3;
                int c = idx & 7;
                CP16(tb + (r * GPITCH + c * 8) * 2,
                     s + (size_t)(rb + r) * K + kc * 64 + c * 8);
            }
        }
        CP_COMMIT();
    };

    load_chunk(0, 0);

    for (int kc = 0; kc < nc; kc++) {
        CP_WAIT0();
        __syncthreads();
        if (kc + 1 < nc) load_chunk(kc + 1, (kc + 1) & 1);

        const uint32_t sb = sbase + (kc & 1) * GSTAGE;
        const uint32_t sA = sb;
        const uint32_t sW = sb + GT_B;

#pragma unroll
        for (int kk = 0; kk < 4; kk++) {
            const uint32_t kByte = kk * 32;
            uint32_t ah[2][4];
#pragma unroll
            for (int mi = 0; mi < 2; mi++) {
                uint32_t ao = aOff + mi * 16 * GPITCH * 2 + kByte;
                LDM4(ah[mi][0], ah[mi][1], ah[mi][2], ah[mi][3], sA + ao);
            }
#pragma unroll
            for (int nb2 = 0; nb2 < 4; nb2++) {
                uint32_t bo = bOff + nb2 * 16 * GPITCH * 2 + kByte;
                uint32_t bh[4];
                LDM4(bh[0], bh[1], bh[2], bh[3], sW + bo);
#pragma unroll
                for (int mi = 0; mi < 2; mi++) {
                    MMA16816(acc[mi][nb2 * 2 + 0], ah[mi], bh[0], bh[1]);
                    MMA16816(acc[mi][nb2 * 2 + 1], ah[mi], bh[2], bh[3]);
                }
            }
        }
    }

    const int g  = lane >> 2;
    const int tc = (lane & 3) * 2;
#pragma unroll
    for (int mi = 0; mi < 2; mi++) {
#pragma unroll
        for (int nb = 0; nb < 8; nb++) {
            int col = colBase + wn + nb * 8 + tc;
            float b0 = bias[col], b1 = bias[col + 1];
            int row0 = rowBase + wm + mi * 16 + g;
            float y0 = (acc[mi][nb][0] + b0) * osc, y1 = (acc[mi][nb][1] + b1) * osc;
            float y2 = (acc[mi][nb][2] + b0) * osc, y3 = (acc[mi][nb][3] + b1) * osc;
            if (Cf) {
                float2 o0 = {y0, y1};
                *(float2*)&Cf[(size_t)row0 * N + col] = o0;
                float2 o1 = {y2, y3};
                *(float2*)&Cf[(size_t)(row0 + 8) * N + col] = o1;
            } else if (Clo) {
                uint32_t h, l;
                split2h(y0, y1, h, l);
                *(uint32_t*)&Chi[(size_t)row0 * N + col] = h;
                *(uint32_t*)&Clo[(size_t)row0 * N + col] = l;
                split2h(y2, y3, h, l);
                *(uint32_t*)&Chi[(size_t)(row0 + 8) * N + col] = h;
                *(uint32_t*)&Clo[(size_t)(row0 + 8) * N + col] = l;
            } else {
                __half2 h0 = __floats2half2_rn(y0, y1);
                *(uint32_t*)&Chi[(size_t)row0 * N + col] = *(uint32_t*)&h0;
                __half2 h1 = __floats2half2_rn(y2, y3);
                *(uint32_t*)&Chi[(size_t)(row0 + 8) * N + col] = *(uint32_t*)&h1;
            }
        }
    }
}

// ---------------------------------------------------------------------------
// fp16 flash attention, log2-domain softmax (MUFU EX2). Q dual (pre-scaled
// by 0.125*log2e), K/V single, P single, Y single. BQ=128, BK=64, 8 warps.
// 3-stage cp.async KV pipeline (R11 config), no occupancy cap.
// ---------------------------------------------------------------------------
#define AP 72
#define AKV_T (64 * AP * 2)              // 9216
#define ASTG  (2 * AKV_T)                // 18432 (Kh + Vh)
#define AQ_B  (128 * AP * 2)             // 18432
#define AKV_B (2 * AQ_B)                 // 36864
#define APAD_B (AKV_B + 3 * ASTG)        // 92160
#define ATTN_SMEM (APAD_B + 3 * 64 * 4)  // 92928

__global__ __launch_bounds__(256) void attn_mma(
    const __half* __restrict__ Qh, const __half* __restrict__ Ql,
    const __half* __restrict__ Kh, const __half* __restrict__ Vh,
    const int* __restrict__ msk,
    __half* __restrict__ Yh)
{
    extern __shared__ char sraw[];
    float* pads = (float*)(sraw + APAD_B);

    const int tid  = threadIdx.x;
    const int lane = tid & 31;
    const int wid  = tid >> 5;
    const int wm   = wid * 16;
    const int qt   = gridDim.x - 1 - blockIdx.x;   // heavy tiles first
    const int bh   = blockIdx.y;
    const int b    = bh / HH;
    const int h    = bh % HH;

    const uint32_t sbase = smem_u32(sraw);
    const uint32_t sQH = sbase, sQL = sbase + AQ_B;

    auto load_kv = [&](int jt, int stage) {
        const size_t krow0 = (size_t)b * LL + (size_t)jt * 64;
        const uint32_t sb = sbase + AKV_B + stage * ASTG;
#pragma unroll
        for (int i = 0; i < 2; i++) {
            int idx = tid + i * 256;      // 0..511
            int r = idx >> 3;
            int c = idx & 7;
            const size_t gsrc = (krow0 + r) * DD + h * DH + c * 8;
            uint32_t so = (r * AP + c * 8) * 2;
            CP16(sb + so,          Kh + gsrc);
            CP16(sb + AKV_T + so,  Vh + gsrc);
        }
        CP_COMMIT();
    };

    // Q tile (128 x 64) hi/lo
    const size_t qrow0 = (size_t)b * LL + (size_t)qt * 128;
#pragma unroll
    for (int i = 0; i < 4; i++) {
        int idx = tid + i * 256;
        int r = idx >> 3;
        int c = idx & 7;
        size_t gsrc = (qrow0 + r) * DD + h * DH + c * 8;
        CP16(sQH + (r * AP + c * 8) * 2, Qh + gsrc);
        CP16(sQL + (r * AP + c * 8) * 2, Ql + gsrc);
    }
    CP_COMMIT();
    const int jtMax = 2 * qt + 1;
    load_kv(0, 0);
    if (1 <= jtMax) load_kv(1, 1); else CP_COMMIT();

    const uint32_t aOff = ((uint32_t)(wm + (lane & 15)) * AP + ((lane >> 4) << 3)) * 2;
    const uint32_t bOff = ((uint32_t)((lane & 7) + ((lane >> 4) << 3)) * AP
                          + (((lane >> 3) & 1) << 3)) * 2;
    const uint32_t vOff = ((uint32_t)(((lane >> 3) & 1) * 8 + (lane & 7)) * AP
                          + ((lane >> 4) << 3)) * 2;

    const int g   = lane >> 2;
    const int tc2 = (lane & 3) * 2;
    const int qg0 = qt * 128 + wm + g;
    const int qg1 = qg0 + 8;

    float m0 = -1e30f, m1 = -1e30f, l0 = 0.0f, l1 = 0.0f;
    float oacc[8][4];
#pragma unroll
    for (int i = 0; i < 8; i++)
#pragma unroll
        for (int v = 0; v < 4; v++) oacc[i][v] = 0.0f;

    for (int jt = 0; jt <= jtMax; jt++) {
        const int cur = jt % 3;
        if (tid < 64)
            pads[cur * 64 + tid] =
                (1.0f - (float)msk[b * LL + jt * 64 + tid]) * NEGV2;

        CP_WAIT1();
        __syncthreads();
        if (jt + 2 <= jtMax) load_kv(jt + 2, (jt + 2) % 3);

        const uint32_t sb  = sbase + AKV_B + cur * ASTG;
        const uint32_t sKH = sb;
        const uint32_t sVH = sb + AKV_T;
        const float* padc = pads + cur * 64;

        // ---- S = (Qh+Ql) @ Kh^T  (log2-domain: Q pre-scaled by s*log2e) ----
        float sacc[8][4];
#pragma unroll
        for (int i = 0; i < 8; i++)
#pragma unroll
            for (int v = 0; v < 4; v++) sacc[i][v] = 0.0f;

#pragma unroll
        for (int kk = 0; kk < 4; kk++) {
            const uint32_t kByte = kk * 32;
            uint32_t ah[4], al[4];
            LDM4(ah[0], ah[1], ah[2], ah[3], sQH + aOff + kByte);
            LDM4(al[0], al[1], al[2], al[3], sQL + aOff + kByte);
#pragma unroll
            for (int nb2 = 0; nb2 < 4; nb2++) {
                uint32_t bo = bOff + nb2 * 16 * AP * 2 + kByte;
                uint32_t kh[4];
                LDM4(kh[0], kh[1], kh[2], kh[3], sKH + bo);
                MMA16816(sacc[nb2 * 2 + 0], ah, kh[0], kh[1]);
                MMA16816(sacc[nb2 * 2 + 1], ah, kh[2], kh[3]);
                MMA16816(sacc[nb2 * 2 + 0], al, kh[0], kh[1]);
                MMA16816(sacc[nb2 * 2 + 1], al, kh[2], kh[3]);
            }
        }

        // ---- causal (warp-uniform skip for interior tiles) + pad mask ----
        if (jt * 64 + 63 > qt * 128 + wm) {
#pragma unroll
            for (int nb = 0; nb < 8; nb++) {
                int kgA = jt * 64 + nb * 8 + tc2;
                float p0 = padc[nb * 8 + tc2];
                float p1 = padc[nb * 8 + tc2 + 1];
                float v0 = sacc[nb][0]; if (kgA     > qg0) v0 = NEGV2; v0 += p0;
                float v1 = sacc[nb][1]; if (kgA + 1 > qg0) v1 = NEGV2; v1 += p1;
                float v2 = sacc[nb][2]; if (kgA     > qg1) v2 = NEGV2; v2 += p0;
                float v3 = sacc[nb][3]; if (kgA + 1 > qg1) v3 = NEGV2; v3 += p1;
                sacc[nb][0] = v0; sacc[nb][1] = v1; sacc[nb][2] = v2; sacc[nb][3] = v3;
            }
        } else {
#pragma unroll
            for (int nb = 0; nb < 8; nb++) {
                float p0 = padc[nb * 8 + tc2];
                float p1 = padc[nb * 8 + tc2 + 1];
                sacc[nb][0] += p0; sacc[nb][1] += p1;
                sacc[nb][2] += p0; sacc[nb][3] += p1;
            }
        }

        // ---- online softmax (base-2, MUFU EX2) ----
        float rmax0 = -1e30f, rmax1 = -1e30f;
#pragma unroll
        for (int nb = 0; nb < 8; nb++) {
            rmax0 = fmaxf(rmax0, fmaxf(sacc[nb][0], sacc[nb][1]));
            rmax1 = fmaxf(rmax1, fmaxf(sacc[nb][2], sacc[nb][3]));
        }
#pragma unroll
        for (int o = 1; o <= 2; o <<= 1) {
            rmax0 = fmaxf(rmax0, __shfl_xor_sync(0xffffffffu, rmax0, o));
            rmax1 = fmaxf(rmax1, __shfl_xor_sync(0xffffffffu, rmax1, o));
        }
        float m0n = fmaxf(m0, rmax0), m1n = fmaxf(m1, rmax1);
        float a0 = ex2(m0 - m0n), a1 = ex2(m1 - m1n);
        float sum0 = 0.0f, sum1 = 0.0f;
#pragma unroll
        for (int nb = 0; nb < 8; nb++) {
            sacc[nb][0] = ex2(sacc[nb][0] - m0n);
            sacc[nb][1] = ex2(sacc[nb][1] - m0n);
            sacc[nb][2] = ex2(sacc[nb][2] - m1n);
            sacc[nb][3] = ex2(sacc[nb][3] - m1n);
            sum0 += sacc[nb][0] + sacc[nb][1];
            sum1 += sacc[nb][2] + sacc[nb][3];
        }
#pragma unroll
        for (int o = 1; o <= 2; o <<= 1) {
            sum0 += __shfl_xor_sync(0xffffffffu, sum0, o);
            sum1 += __shfl_xor_sync(0xffffffffu, sum1, o);
        }
        l0 = l0 * a0 + sum0; m0 = m0n;
        l1 = l1 * a1 + sum1; m1 = m1n;
#pragma unroll
        for (int nb = 0; nb < 8; nb++) {
            oacc[nb][0] *= a0; oacc[nb][1] *= a0;
            oacc[nb][2] *= a1; oacc[nb][3] *= a1;
        }

        // ---- O += P @ Vh (P single fp16) ----
#pragma unroll
        for (int kb = 0; kb < 4; kb++) {
            uint32_t ph[4];
            {
                __half2 t0 = __floats2half2_rn(sacc[2 * kb][0],     sacc[2 * kb][1]);
                __half2 t1 = __floats2half2_rn(sacc[2 * kb][2],     sacc[2 * kb][3]);
                __half2 t2 = __floats2half2_rn(sacc[2 * kb + 1][0], sacc[2 * kb + 1][1]);
                __half2 t3 = __floats2half2_rn(sacc[2 * kb + 1][2], sacc[2 * kb + 1][3]);
                ph[0] = *(uint32_t*)&t0; ph[1] = *(uint32_t*)&t1;
                ph[2] = *(uint32_t*)&t2; ph[3] = *(uint32_t*)&t3;
            }
#pragma unroll
            for (int nb2 = 0; nb2 < 4; nb2++) {
                uint32_t vo = vOff + (kb * 16 * AP + nb2 * 16) * 2;
                uint32_t vh[4];
                LDMT4(vh[0], vh[1], vh[2], vh[3], sVH + vo);
                MMA16816(oacc[nb2 * 2 + 0], ph, vh[0], vh[1]);
                MMA16816(oacc[nb2 * 2 + 1], ph, vh[2], vh[3]);
            }
        }
    }

    // ---- finalize + write Y (single fp16) ----
    float inv0 = 1.0f / l0, inv1 = 1.0f / l1;
    const size_t row0 = qrow0 + wm + g;
#pragma unroll
    for (int nb = 0; nb < 8; nb++) {
        int col = h * DH + nb * 8 + tc2;
        __half2 h0 = __floats2half2_rn(oacc[nb][0] * inv0, oacc[nb][1] * inv0);
        *(uint32_t*)&Yh[row0 * DD + col] = *(uint32_t*)&h0;
        __half2 h1 = __floats2half2_rn(oacc[nb][2] * inv1, oacc[nb][3] * inv1);
        *(uint32_t*)&Yh[(row0 + 8) * DD + col] = *(uint32_t*)&h1;
    }
}

// ---------------------------------------------------------------------------
extern "C" void kernel_launch(void* const* d_in, const int* in_sizes, int n_in,
                              void* d_out, int out_size)
{
    const float* x  = (const float*)d_in[0];
    const int*   m  = (const int*)d_in[1];
    const float* Wq = (const float*)d_in[2];
    const float* bq = (const float*)d_in[3];
    const float* Wk = (const float*)d_in[4];
    const float* bk = (const float*)d_in[5];
    const float* Wv = (const float*)d_in[6];
    const float* bv = (const float*)d_in[7];
    const float* Wp = (const float*)d_in[8];
    const float* bp = (const float*)d_in[9];
    float* out = (float*)d_out;

    __half *xh, *wh, *qh, *ql, *kh, *vh, *yh;
    cudaGetSymbolAddress((void**)&xh, g_Xh);
    cudaGetSymbolAddress((void**)&wh, g_Wh);
    cudaGetSymbolAddress((void**)&qh, g_Qh);
    cudaGetSymbolAddress((void**)&ql, g_Ql);
    cudaGetSymbolAddress((void**)&kh, g_Kh);
    cudaGetSymbolAddress((void**)&vh, g_Vh);
    cudaGetSymbolAddress((void**)&yh, g_Yh);

    static bool attr_set = false;
    if (!attr_set) {
        cudaFuncSetAttribute(gemm_mma,
                             cudaFuncAttributeMaxDynamicSharedMemorySize, GEMM_SMEM);
        cudaFuncSetAttribute(attn_mma,
                             cudaFuncAttributeMaxDynamicSharedMemorySize, ATTN_SMEM);
        attr_set = true;
    }

    // One fused conversion launch: 4 weights + 4 quarters of x (NELT==4*WELT)
    CPtrs8 c8;
    c8.src[0] = Wq; c8.dst[0] = wh + 0 * WELT;
    c8.src[1] = Wk; c8.dst[1] = wh + 1 * WELT;
    c8.src[2] = Wv; c8.dst[2] = wh + 2 * WELT;
    c8.src[3] = Wp; c8.dst[3] = wh + 3 * WELT;
    for (int i = 0; i < 4; i++) {
        c8.src[4 + i] = x + (size_t)i * WELT;
        c8.dst[4 + i] = xh + (size_t)i * WELT;
    }
    dim3 cgrid(WELT / 4 / 256, 8);
    conv8<<<cgrid, 256>>>(c8);

    // Fused QKV (z = 0:Q dual out, pre-scaled by 0.125*log2e; 1:K; 2:V)
    GArgs qkv;
    qkv.W[0] = wh + 0 * WELT; qkv.W[1] = wh + 1 * WELT; qkv.W[2] = wh + 2 * WELT;
    qkv.bias[0] = bq; qkv.bias[1] = bk; qkv.bias[2] = bv;
    qkv.oh[0] = qh;  qkv.oh[1] = kh;  qkv.oh[2] = vh;
    qkv.ol[0] = ql;  qkv.ol[1] = nullptr; qkv.ol[2] = nullptr;
    qkv.oscale[0] = 0.125f * LOG2E; qkv.oscale[1] = 1.0f; qkv.oscale[2] = 1.0f;
    dim3 qgrid(DD / 128, NTOK / 128, 3);   // (8, 32, 3)
    gemm_mma<<<qgrid, 256, GEMM_SMEM>>>(xh, qkv, nullptr, NTOK, DD, DD);

    dim3 agrid(LL / 128, BB * HH);         // (16, 32)
    attn_mma<<<agrid, 256, ATTN_SMEM>>>(qh, ql, kh, vh, m, yh);

    GArgs proj;
    proj.W[0] = wh + 3 * WELT; proj.W[1] = nullptr; proj.W[2] = nullptr;
    proj.bias[0] = bp; proj.bias[1] = nullptr; proj.bias[2] = nullptr;
    proj.oh[0] = nullptr; proj.oh[1] = nullptr; proj.oh[2] = nullptr;
    proj.ol[0] = nullptr; proj.ol[1] = nullptr; proj.ol[2] = nullptr;
    proj.oscale[0] = 1.0f; proj.oscale[1] = 1.0f; proj.oscale[2] = 1.0f;
    dim3 pgrid(DD / 128, NTOK / 128, 1);   // (8, 32, 1)
    gemm_mma<<<pgrid, 256, GEMM_SMEM>>>(yh, proj, out, NTOK, DD, DD);
}

// round 16
// speedup vs baseline: 1.1000x; 1.0822x over previous
#include <cuda_runtime.h>
#include <cuda_fp16.h>
#include <cstdint>
#include <math.h>

#define BB 2
#define LL 2048
#define DD 1024
#define HH 16
#define DH 64
#define NEGV -10000.0f
#define LOG2E 1.44269504088896f
#define NEGV2 (-14426.9504f)    // NEGV * LOG2E

#define NTOK (BB * LL)          // 4096
#define NELT (BB * LL * DD)     // 4194304
#define WELT (DD * DD)          // 1048576

// ---------------------------------------------------------------------------
// Scratch (__device__ globals per allocation rules)
// ---------------------------------------------------------------------------
__device__ __half g_Xh[NELT];       // x single fp16
__device__ __half g_Wh[4 * WELT];   // Wq,Wk,Wv,Wp single fp16
__device__ __half g_Qh[NELT];       // pre-scaled by 0.125*log2e, hi
__device__ __half g_Ql[NELT];       // pre-scaled, lo residual
__device__ __half g_Kh[NELT];
__device__ __half g_Vh[NELT];
__device__ __half g_Yh[NELT];       // attention out, single fp16

// ---------------------------------------------------------------------------
// PTX helpers (non-'a' features: ldmatrix, mma.sync f16, cp.async)
// ---------------------------------------------------------------------------
__device__ __forceinline__ uint32_t smem_u32(const void* p) {
    uint32_t a;
    asm("{ .reg .u64 t; cvta.to.shared.u64 t, %1; cvt.u32.u64 %0, t; }"
        : "=r"(a) : "l"(p));
    return a;
}

// single-MUFU base-2 exponential (EX2)
__device__ __forceinline__ float ex2(float x) {
    float r;
    asm("ex2.approx.ftz.f32 %0, %1;" : "=f"(r) : "f"(x));
    return r;
}

#define LDM4(r0, r1, r2, r3, addr) \
    asm volatile("ldmatrix.sync.aligned.m8n8.x4.shared.b16 {%0,%1,%2,%3}, [%4];" \
                 : "=r"(r0), "=r"(r1), "=r"(r2), "=r"(r3) : "r"(addr))

#define LDMT4(r0, r1, r2, r3, addr) \
    asm volatile("ldmatrix.sync.aligned.m8n8.x4.trans.shared.b16 {%0,%1,%2,%3}, [%4];" \
                 : "=r"(r0), "=r"(r1), "=r"(r2), "=r"(r3) : "r"(addr))

#define MMA16816(acc, a, b0, b1) \
    asm volatile("mma.sync.aligned.m16n8k16.row.col.f32.f16.f16.f32 " \
                 "{%0,%1,%2,%3}, {%4,%5,%6,%7}, {%8,%9}, {%0,%1,%2,%3};" \
                 : "+f"((acc)[0]), "+f"((acc)[1]), "+f"((acc)[2]), "+f"((acc)[3]) \
                 : "r"((a)[0]), "r"((a)[1]), "r"((a)[2]), "r"((a)[3]), \
                   "r"(b0), "r"(b1))

#define CP16(dst, src) \
    asm volatile("cp.async.cg.shared.global [%0], [%1], 16;" \
                 :: "r"(dst), "l"(src) : "memory")
#define CP_COMMIT() asm volatile("cp.async.commit_group;" ::: "memory")
#define CP_WAIT0()  asm volatile("cp.async.wait_group 0;" ::: "memory")
#define CP_WAIT1()  asm volatile("cp.async.wait_group 1;" ::: "memory")

// split a,b into packed fp16 hi pair + residual lo pair
__device__ __forceinline__ void split2h(float a, float b, uint32_t& hi, uint32_t& lo) {
    __half2 h = __floats2half2_rn(a, b);
    __half2 l = __floats2half2_rn(a - __half2float(h.x), b - __half2float(h.y));
    hi = *(uint32_t*)&h;
    lo = *(uint32_t*)&l;
}

// ---------------------------------------------------------------------------
// conversions (R11 layout: one for x, one gridded for weights)
// ---------------------------------------------------------------------------
__global__ __launch_bounds__(256) void conv_one(
    const float* __restrict__ src, __half* __restrict__ dst, int n)
{
    int idx = (blockIdx.x * 256 + threadIdx.x) * 4;
    if (idx >= n) return;
    float4 v = *(const float4*)&src[idx];
    __half h[4] = {__float2half_rn(v.x), __float2half_rn(v.y),
                   __float2half_rn(v.z), __float2half_rn(v.w)};
    *(uint2*)&dst[idx] = *(uint2*)h;
}

struct WPtrs { const float* src[4]; };

__global__ __launch_bounds__(256) void conv_w(
    WPtrs wp, __half* __restrict__ dst)
{
    const float* src = wp.src[blockIdx.y];
    __half* d = dst + (size_t)blockIdx.y * WELT;
    int idx = (blockIdx.x * 256 + threadIdx.x) * 4;
    if (idx >= WELT) return;
    float4 v = *(const float4*)&src[idx];
    __half h[4] = {__float2half_rn(v.x), __float2half_rn(v.y),
                   __float2half_rn(v.z), __float2half_rn(v.w)};
    *(uint2*)&d[idx] = *(uint2*)h;
}

// ---------------------------------------------------------------------------
// fp16 1-term GEMM: C = A @ W^T + bias (A, W single fp16).
// Tile 128x128, BK=64, 8 warps (4Mx2N), warp tile 32x64. Pitch 72.
// 2-stage cp.async, one barrier per chunk. Fused QKV via blockIdx.z.
// ---------------------------------------------------------------------------
#define GPITCH 72
#define GT_B   (128 * GPITCH * 2)        // 18432
#define GSTAGE (2 * GT_B)                // 36864 (A, W)
#define GEMM_SMEM (2 * GSTAGE)           // 73728

struct GArgs {
    const __half* W[3];
    const float*  bias[3];
    __half* oh[3];
    __half* ol[3];
    float oscale[3];
};

__global__ __launch_bounds__(256) void gemm_mma(
    const __half* __restrict__ A,
    GArgs args, float* __restrict__ Cf, int M, int N, int K)
{
    extern __shared__ char sraw[];

    const int z = blockIdx.z;
    const __half* W   = args.W[z];
    const float* bias = args.bias[z];
    __half* Chi = args.oh[z];
    __half* Clo = args.ol[z];
    const float osc = args.oscale[z];

    const int tid  = threadIdx.x;
    const int lane = tid & 31;
    const int wid  = tid >> 5;
    const int wm   = (wid >> 1) * 32;
    const int wn   = (wid & 1) * 64;
    const int rowBase = blockIdx.y * 128;
    const int colBase = blockIdx.x * 128;

    const uint32_t sbase = smem_u32(sraw);

    const uint32_t aOff = ((uint32_t)(wm + (lane & 15)) * GPITCH + ((lane >> 4) << 3)) * 2;
    const uint32_t bOff = ((uint32_t)(wn + (lane & 7) + ((lane >> 4) << 3)) * GPITCH
                          + (((lane >> 3) & 1) << 3)) * 2;

    float acc[2][8][4];
#pragma unroll
    for (int i = 0; i < 2; i++)
#pragma unroll
        for (int j = 0; j < 8; j++)
#pragma unroll
            for (int v = 0; v < 4; v++) acc[i][j][v] = 0.0f;

    const int nc = K >> 6;

    auto load_chunk = [&](int kc, int stage) {
        const uint32_t sb = sbase + stage * GSTAGE;
        const __half* srcs[2] = {A, W};
        const int rbs[2] = {rowBase, colBase};
#pragma unroll
        for (int t = 0; t < 2; t++) {
            const __half* s = srcs[t];
            const int rb = rbs[t];
            const uint32_t tb = sb + t * GT_B;
#pragma unroll
            for (int i = 0; i < 4; i++) {
                int idx = tid + i * 256;
                int r = idx >> 3;
                int c = idx & 7;
                CP16(tb + (r * GPITCH + c * 8) * 2,
                     s + (size_t)(rb + r) * K + kc * 64 + c * 8);
            }
        }
        CP_COMMIT();
    };

    load_chunk(0, 0);

    for (int kc = 0; kc < nc; kc++) {
        CP_WAIT0();
        __syncthreads();
        if (kc + 1 < nc) load_chunk(kc + 1, (kc + 1) & 1);

        const uint32_t sb = sbase + (kc & 1) * GSTAGE;
        const uint32_t sA = sb;
        const uint32_t sW = sb + GT_B;

#pragma unroll
        for (int kk = 0; kk < 4; kk++) {
            const uint32_t kByte = kk * 32;
            uint32_t ah[2][4];
#pragma unroll
            for (int mi = 0; mi < 2; mi++) {
                uint32_t ao = aOff + mi * 16 * GPITCH * 2 + kByte;
                LDM4(ah[mi][0], ah[mi][1], ah[mi][2], ah[mi][3], sA + ao);
            }
#pragma unroll
            for (int nb2 = 0; nb2 < 4; nb2++) {
                uint32_t bo = bOff + nb2 * 16 * GPITCH * 2 + kByte;
                uint32_t bh[4];
                LDM4(bh[0], bh[1], bh[2], bh[3], sW + bo);
#pragma unroll
                for (int mi = 0; mi < 2; mi++) {
                    MMA16816(acc[mi][nb2 * 2 + 0], ah[mi], bh[0], bh[1]);
                    MMA16816(acc[mi][nb2 * 2 + 1], ah[mi], bh[2], bh[3]);
                }
            }
        }
    }

    const int g  = lane >> 2;
    const int tc = (lane & 3) * 2;
#pragma unroll
    for (int mi = 0; mi < 2; mi++) {
#pragma unroll
        for (int nb = 0; nb < 8; nb++) {
            int col = colBase + wn + nb * 8 + tc;
            float b0 = bias[col], b1 = bias[col + 1];
            int row0 = rowBase + wm + mi * 16 + g;
            float y0 = (acc[mi][nb][0] + b0) * osc, y1 = (acc[mi][nb][1] + b1) * osc;
            float y2 = (acc[mi][nb][2] + b0) * osc, y3 = (acc[mi][nb][3] + b1) * osc;
            if (Cf) {
                float2 o0 = {y0, y1};
                *(float2*)&Cf[(size_t)row0 * N + col] = o0;
                float2 o1 = {y2, y3};
                *(float2*)&Cf[(size_t)(row0 + 8) * N + col] = o1;
            } else if (Clo) {
                uint32_t h, l;
                split2h(y0, y1, h, l);
                *(uint32_t*)&Chi[(size_t)row0 * N + col] = h;
                *(uint32_t*)&Clo[(size_t)row0 * N + col] = l;
                split2h(y2, y3, h, l);
                *(uint32_t*)&Chi[(size_t)(row0 + 8) * N + col] = h;
                *(uint32_t*)&Clo[(size_t)(row0 + 8) * N + col] = l;
            } else {
                __half2 h0 = __floats2half2_rn(y0, y1);
                *(uint32_t*)&Chi[(size_t)row0 * N + col] = *(uint32_t*)&h0;
                __half2 h1 = __floats2half2_rn(y2, y3);
                *(uint32_t*)&Chi[(size_t)(row0 + 8) * N + col] = *(uint32_t*)&h1;
            }
        }
    }
}

// ---------------------------------------------------------------------------
// fp16 flash attention, log2-domain softmax (MUFU EX2), DEFERRED row-sum
// reduction (per-lane partial l, reduced once at finalize). Q dual
// (pre-scaled by 0.125*log2e), K/V single, P single, Y single.
// BQ=128, BK=64, 8 warps. 3-stage cp.async KV pipeline (R11 config).
// ---------------------------------------------------------------------------
#define AP 72
#define AKV_T (64 * AP * 2)              // 9216
#define ASTG  (2 * AKV_T)                // 18432 (Kh + Vh)
#define AQ_B  (128 * AP * 2)             // 18432
#define AKV_B (2 * AQ_B)                 // 36864
#define APAD_B (AKV_B + 3 * ASTG)        // 92160
#define ATTN_SMEM (APAD_B + 3 * 64 * 4)  // 92928

__global__ __launch_bounds__(256) void attn_mma(
    const __half* __restrict__ Qh, const __half* __restrict__ Ql,
    const __half* __restrict__ Kh, const __half* __restrict__ Vh,
    const int* __restrict__ msk,
    __half* __restrict__ Yh)
{
    extern __shared__ char sraw[];
    float* pads = (float*)(sraw + APAD_B);

    const int tid  = threadIdx.x;
    const int lane = tid & 31;
    const int wid  = tid >> 5;
    const int wm   = wid * 16;
    const int qt   = gridDim.x - 1 - blockIdx.x;   // heavy tiles first
    const int bh   = blockIdx.y;
    const int b    = bh / HH;
    const int h    = bh % HH;

    const uint32_t sbase = smem_u32(sraw);
    const uint32_t sQH = sbase, sQL = sbase + AQ_B;

    auto load_kv = [&](int jt, int stage) {
        const size_t krow0 = (size_t)b * LL + (size_t)jt * 64;
        const uint32_t sb = sbase + AKV_B + stage * ASTG;
#pragma unroll
        for (int i = 0; i < 2; i++) {
            int idx = tid + i * 256;      // 0..511
            int r = idx >> 3;
            int c = idx & 7;
            const size_t gsrc = (krow0 + r) * DD + h * DH + c * 8;
            uint32_t so = (r * AP + c * 8) * 2;
            CP16(sb + so,          Kh + gsrc);
            CP16(sb + AKV_T + so,  Vh + gsrc);
        }
        CP_COMMIT();
    };

    // Q tile (128 x 64) hi/lo
    const size_t qrow0 = (size_t)b * LL + (size_t)qt * 128;
#pragma unroll
    for (int i = 0; i < 4; i++) {
        int idx = tid + i * 256;
        int r = idx >> 3;
        int c = idx & 7;
        size_t gsrc = (qrow0 + r) * DD + h * DH + c * 8;
        CP16(sQH + (r * AP + c * 8) * 2, Qh + gsrc);
        CP16(sQL + (r * AP + c * 8) * 2, Ql + gsrc);
    }
    CP_COMMIT();
    const int jtMax = 2 * qt + 1;
    load_kv(0, 0);
    if (1 <= jtMax) load_kv(1, 1); else CP_COMMIT();

    const uint32_t aOff = ((uint32_t)(wm + (lane & 15)) * AP + ((lane >> 4) << 3)) * 2;
    const uint32_t bOff = ((uint32_t)((lane & 7) + ((lane >> 4) << 3)) * AP
                          + (((lane >> 3) & 1) << 3)) * 2;
    const uint32_t vOff = ((uint32_t)(((lane >> 3) & 1) * 8 + (lane & 7)) * AP
                          + ((lane >> 4) << 3)) * 2;

    const int g   = lane >> 2;
    const int tc2 = (lane & 3) * 2;
    const int qg0 = qt * 128 + wm + g;
    const int qg1 = qg0 + 8;

    // l0/l1 are PER-LANE PARTIAL sums (this lane's 2 columns); reduced at end.
    float m0 = -1e30f, m1 = -1e30f, l0 = 0.0f, l1 = 0.0f;
    float oacc[8][4];
#pragma unroll
    for (int i = 0; i < 8; i++)
#pragma unroll
        for (int v = 0; v < 4; v++) oacc[i][v] = 0.0f;

    for (int jt = 0; jt <= jtMax; jt++) {
        const int cur = jt % 3;
        if (tid < 64)
            pads[cur * 64 + tid] =
                (1.0f - (float)msk[b * LL + jt * 64 + tid]) * NEGV2;

        CP_WAIT1();
        __syncthreads();
        if (jt + 2 <= jtMax) load_kv(jt + 2, (jt + 2) % 3);

        const uint32_t sb  = sbase + AKV_B + cur * ASTG;
        const uint32_t sKH = sb;
        const uint32_t sVH = sb + AKV_T;
        const float* padc = pads + cur * 64;

        // ---- S = (Qh+Ql) @ Kh^T  (log2-domain: Q pre-scaled by s*log2e) ----
        float sacc[8][4];
#pragma unroll
        for (int i = 0; i < 8; i++)
#pragma unroll
            for (int v = 0; v < 4; v++) sacc[i][v] = 0.0f;

#pragma unroll
        for (int kk = 0; kk < 4; kk++) {
            const uint32_t kByte = kk * 32;
            uint32_t ah[4], al[4];
            LDM4(ah[0], ah[1], ah[2], ah[3], sQH + aOff + kByte);
            LDM4(al[0], al[1], al[2], al[3], sQL + aOff + kByte);
#pragma unroll
            for (int nb2 = 0; nb2 < 4; nb2++) {
                uint32_t bo = bOff + nb2 * 16 * AP * 2 + kByte;
                uint32_t kh[4];
                LDM4(kh[0], kh[1], kh[2], kh[3], sKH + bo);
                MMA16816(sacc[nb2 * 2 + 0], ah, kh[0], kh[1]);
                MMA16816(sacc[nb2 * 2 + 1], ah, kh[2], kh[3]);
                MMA16816(sacc[nb2 * 2 + 0], al, kh[0], kh[1]);
                MMA16816(sacc[nb2 * 2 + 1], al, kh[2], kh[3]);
            }
        }

        // ---- causal (warp-uniform skip for interior tiles) + pad mask ----
        if (jt * 64 + 63 > qt * 128 + wm) {
#pragma unroll
            for (int nb = 0; nb < 8; nb++) {
                int kgA = jt * 64 + nb * 8 + tc2;
                float p0 = padc[nb * 8 + tc2];
                float p1 = padc[nb * 8 + tc2 + 1];
                float v0 = sacc[nb][0]; if (kgA     > qg0) v0 = NEGV2; v0 += p0;
                float v1 = sacc[nb][1]; if (kgA + 1 > qg0) v1 = NEGV2; v1 += p1;
                float v2 = sacc[nb][2]; if (kgA     > qg1) v2 = NEGV2; v2 += p0;
                float v3 = sacc[nb][3]; if (kgA + 1 > qg1) v3 = NEGV2; v3 += p1;
                sacc[nb][0] = v0; sacc[nb][1] = v1; sacc[nb][2] = v2; sacc[nb][3] = v3;
            }
        } else {
#pragma unroll
            for (int nb = 0; nb < 8; nb++) {
                float p0 = padc[nb * 8 + tc2];
                float p1 = padc[nb * 8 + tc2 + 1];
                sacc[nb][0] += p0; sacc[nb][1] += p1;
                sacc[nb][2] += p0; sacc[nb][3] += p1;
            }
        }

        // ---- online softmax (base-2, MUFU EX2, deferred l reduction) ----
        float rmax0 = -1e30f, rmax1 = -1e30f;
#pragma unroll
        for (int nb = 0; nb < 8; nb++) {
            rmax0 = fmaxf(rmax0, fmaxf(sacc[nb][0], sacc[nb][1]));
            rmax1 = fmaxf(rmax1, fmaxf(sacc[nb][2], sacc[nb][3]));
        }
#pragma unroll
        for (int o = 1; o <= 2; o <<= 1) {
            rmax0 = fmaxf(rmax0, __shfl_xor_sync(0xffffffffu, rmax0, o));
            rmax1 = fmaxf(rmax1, __shfl_xor_sync(0xffffffffu, rmax1, o));
        }
        float m0n = fmaxf(m0, rmax0), m1n = fmaxf(m1, rmax1);
        float a0 = ex2(m0 - m0n), a1 = ex2(m1 - m1n);
        float sum0 = 0.0f, sum1 = 0.0f;
#pragma unroll
        for (int nb = 0; nb < 8; nb++) {
            sacc[nb][0] = ex2(sacc[nb][0] - m0n);
            sacc[nb][1] = ex2(sacc[nb][1] - m0n);
            sacc[nb][2] = ex2(sacc[nb][2] - m1n);
            sacc[nb][3] = ex2(sacc[nb][3] - m1n);
            sum0 += sacc[nb][0] + sacc[nb][1];
            sum1 += sacc[nb][2] + sacc[nb][3];
        }
        // NO cross-lane sum shuffle here: l stays lane-partial (a0/a1 are
        // row-uniform because the max WAS reduced). Reduced once at finalize.
        l0 = fmaf(l0, a0, sum0); m0 = m0n;
        l1 = fmaf(l1, a1, sum1); m1 = m1n;
#pragma unroll
        for (int nb = 0; nb < 8; nb++) {
            oacc[nb][0] *= a0; oacc[nb][1] *= a0;
            oacc[nb][2] *= a1; oacc[nb][3] *= a1;
        }

        // ---- O += P @ Vh (P single fp16) ----
#pragma unroll
        for (int kb = 0; kb < 4; kb++) {
            uint32_t ph[4];
            {
                __half2 t0 = __floats2half2_rn(sacc[2 * kb][0],     sacc[2 * kb][1]);
                __half2 t1 = __floats2half2_rn(sacc[2 * kb][2],     sacc[2 * kb][3]);
                __half2 t2 = __floats2half2_rn(sacc[2 * kb + 1][0], sacc[2 * kb + 1][1]);
                __half2 t3 = __floats2half2_rn(sacc[2 * kb + 1][2], sacc[2 * kb + 1][3]);
                ph[0] = *(uint32_t*)&t0; ph[1] = *(uint32_t*)&t1;
                ph[2] = *(uint32_t*)&t2; ph[3] = *(uint32_t*)&t3;
            }
#pragma unroll
            for (int nb2 = 0; nb2 < 4; nb2++) {
                uint32_t vo = vOff + (kb * 16 * AP + nb2 * 16) * 2;
                uint32_t vh[4];
                LDMT4(vh[0], vh[1], vh[2], vh[3], sVH + vo);
                MMA16816(oacc[nb2 * 2 + 0], ph, vh[0], vh[1]);
                MMA16816(oacc[nb2 * 2 + 1], ph, vh[2], vh[3]);
            }
        }
    }

    // ---- finalize: reduce lane-partial l across the 4-lane row group ----
#pragma unroll
    for (int o = 1; o <= 2; o <<= 1) {
        l0 += __shfl_xor_sync(0xffffffffu, l0, o);
        l1 += __shfl_xor_sync(0xffffffffu, l1, o);
    }
    float inv0 = 1.0f / l0, inv1 = 1.0f / l1;
    const size_t row0 = qrow0 + wm + g;
#pragma unroll
    for (int nb = 0; nb < 8; nb++) {
        int col = h * DH + nb * 8 + tc2;
        __half2 h0 = __floats2half2_rn(oacc[nb][0] * inv0, oacc[nb][1] * inv0);
        *(uint32_t*)&Yh[row0 * DD + col] = *(uint32_t*)&h0;
        __half2 h1 = __floats2half2_rn(oacc[nb][2] * inv1, oacc[nb][3] * inv1);
        *(uint32_t*)&Yh[(row0 + 8) * DD + col] = *(uint32_t*)&h1;
    }
}

// ---------------------------------------------------------------------------
extern "C" void kernel_launch(void* const* d_in, const int* in_sizes, int n_in,
                              void* d_out, int out_size)
{
    const float* x  = (const float*)d_in[0];
    const int*   m  = (const int*)d_in[1];
    const float* Wq = (const float*)d_in[2];
    const float* bq = (const float*)d_in[3];
    const float* Wk = (const float*)d_in[4];
    const float* bk = (const float*)d_in[5];
    const float* Wv = (const float*)d_in[6];
    const float* bv = (const float*)d_in[7];
    const float* Wp = (const float*)d_in[8];
    const float* bp = (const float*)d_in[9];
    float* out = (float*)d_out;

    __half *xh, *wh, *qh, *ql, *kh, *vh, *yh;
    cudaGetSymbolAddress((void**)&xh, g_Xh);
    cudaGetSymbolAddress((void**)&wh, g_Wh);
    cudaGetSymbolAddress((void**)&qh, g_Qh);
    cudaGetSymbolAddress((void**)&ql, g_Ql);
    cudaGetSymbolAddress((void**)&kh, g_Kh);
    cudaGetSymbolAddress((void**)&vh, g_Vh);
    cudaGetSymbolAddress((void**)&yh, g_Yh);

    static bool attr_set = false;
    if (!attr_set) {
        cudaFuncSetAttribute(gemm_mma,
                             cudaFuncAttributeMaxDynamicSharedMemorySize, GEMM_SMEM);
        cudaFuncSetAttribute(attn_mma,
                             cudaFuncAttributeMaxDynamicSharedMemorySize, ATTN_SMEM);
        attr_set = true;
    }

    conv_one<<<NELT / 4 / 256, 256>>>(x, xh, NELT);
    WPtrs wp;
    wp.src[0] = Wq; wp.src[1] = Wk; wp.src[2] = Wv; wp.src[3] = Wp;
    dim3 wgrid(WELT / 4 / 256, 4);
    conv_w<<<wgrid, 256>>>(wp, wh);

    // Fused QKV (z = 0:Q dual out, pre-scaled by 0.125*log2e; 1:K; 2:V)
    GArgs qkv;
    qkv.W[0] = wh + 0 * WELT; qkv.W[1] = wh + 1 * WELT; qkv.W[2] = wh + 2 * WELT;
    qkv.bias[0] = bq; qkv.bias[1] = bk; qkv.bias[2] = bv;
    qkv.oh[0] = qh;  qkv.oh[1] = kh;  qkv.oh[2] = vh;
    qkv.ol[0] = ql;  qkv.ol[1] = nullptr; qkv.ol[2] = nullptr;
    qkv.oscale[0] = 0.125f * LOG2E; qkv.oscale[1] = 1.0f; qkv.oscale[2] = 1.0f;
    dim3 qgrid(DD / 128, NTOK / 128, 3);   // (8, 32, 3)
    gemm_mma<<<qgrid, 256, GEMM_SMEM>>>(xh, qkv, nullptr, NTOK, DD, DD);

    dim3 agrid(LL / 128, BB * HH);         // (16, 32)
    attn_mma<<<agrid, 256, ATTN_SMEM>>>(qh, ql, kh, vh, m, yh);

    GArgs proj;
    proj.W[0] = wh + 3 * WELT; proj.W[1] = nullptr; proj.W[2] = nullptr;
    proj.bias[0] = bp; proj.bias[1] = nullptr; proj.bias[2] = nullptr;
    proj.oh[0] = nullptr; proj.oh[1] = nullptr; proj.oh[2] = nullptr;
    proj.ol[0] = nullptr; proj.ol[1] = nullptr; proj.ol[2] = nullptr;
    proj.oscale[0] = 1.0f; proj.oscale[1] = 1.0f; proj.oscale[2] = 1.0f;
    dim3 pgrid(DD / 128, NTOK / 128, 1);   // (8, 32, 1)
    gemm_mma<<<pgrid, 256, GEMM_SMEM>>>(yh, proj, out, NTOK, DD, DD);
}